// round 2
// baseline (speedup 1.0000x reference)
#include <cuda_runtime.h>

#define B_     8
#define NODES_ 2048
#define U_     1024
#define IND_   64
#define DD_    128

// Scratch (device globals: allocation-free rule)
__device__ float g_Q[B_ * NODES_ * DD_];              // scaled Q, 8 MB
__device__ float g_K[B_ * U_ * DD_];                  // K (first 1024 nodes), 4 MB
__device__ float g_S[(size_t)B_ * NODES_ * U_];       // scores, 64 MB

// ---------------------------------------------------------------------------
// Kernel 1: Q/K projections.  q = (x@Wq.T + bq) * 1/sqrt(32), k = x@Wk.T + bk
// grid: 2048 blocks (8 batches x 256 row-chunks of 8), 128 threads (one per dd)
// ---------------------------------------------------------------------------
__global__ __launch_bounds__(128) void qk_kernel(
    const float* __restrict__ x,
    const float* __restrict__ Wq, const float* __restrict__ bq,
    const float* __restrict__ Wk, const float* __restrict__ bk)
{
    const int dd  = threadIdx.x;            // 0..127
    const int blk = blockIdx.x;
    const int b   = blk >> 8;               // 256 blocks per batch
    const int n0  = (blk & 255) * 8;

    float4 wq[16], wk[16];
    const float4* Wq4 = reinterpret_cast<const float4*>(Wq) + dd * 16;
    const float4* Wk4 = reinterpret_cast<const float4*>(Wk) + dd * 16;
#pragma unroll
    for (int i = 0; i < 16; i++) { wq[i] = __ldg(Wq4 + i); wk[i] = __ldg(Wk4 + i); }
    const float biasq = __ldg(bq + dd);
    const float biask = __ldg(bk + dd);
    const float inv   = 0.17677669529663689f;   // 1/sqrt(32)

#pragma unroll
    for (int r = 0; r < 8; r++) {
        const int n = n0 + r;
        const float4* xr = reinterpret_cast<const float4*>(x + ((size_t)b * NODES_ + n) * IND_);
        float qa = 0.f, ka = 0.f;
#pragma unroll
        for (int i = 0; i < 16; i++) {
            float4 xv = __ldg(xr + i);
            qa = fmaf(xv.x, wq[i].x, qa); qa = fmaf(xv.y, wq[i].y, qa);
            qa = fmaf(xv.z, wq[i].z, qa); qa = fmaf(xv.w, wq[i].w, qa);
            ka = fmaf(xv.x, wk[i].x, ka); ka = fmaf(xv.y, wk[i].y, ka);
            ka = fmaf(xv.z, wk[i].z, ka); ka = fmaf(xv.w, wk[i].w, ka);
        }
        g_Q[((size_t)b * NODES_ + n) * DD_ + dd] = (qa + biasq) * inv;
        if (n < U_)
            g_K[((size_t)b * U_ + n) * DD_ + dd] = ka + biask;
    }
}

// ---------------------------------------------------------------------------
// Kernel 2: scores.  Per (b,n,u): 4 head-dots (32 dims each), then
//   s = sum_h d_h + sum_o relu( sum_h w[o,h]*d_h + b[o] )
// Tile: 32 n-rows x 128 u-cols per CTA, 256 threads, 4x4 micro-tile.
// u micro is strided (u = uu*32 + tx) for conflict-free LDS.128 (row pad 132).
// ---------------------------------------------------------------------------
#define TN 32
#define TU 128
#define KS 132   // padded row stride in floats (33 x 16B granules; odd mod 8 -> no LDS.128 conflicts)
#define SMEM_BYTES ((TN + TU) * KS * 4)

extern __shared__ float smem2[];

__global__ __launch_bounds__(256, 2) void scores_kernel(
    const float* __restrict__ mlp_w, const float* __restrict__ mlp_b)
{
    float* sQ = smem2;                 // TN x KS
    float* sK = smem2 + TN * KS;       // TU x KS

    const int b  = blockIdx.z;
    const int n0 = blockIdx.y * TN;
    const int u0 = blockIdx.x * TU;
    const int t  = threadIdx.x;

    const float* Qb = g_Q + ((size_t)b * NODES_ + n0) * DD_;
    const float* Kb = g_K + ((size_t)b * U_ + u0) * DD_;

    // cooperative tile loads (float4, coalesced, conflict-free STS)
    for (int i = t; i < TN * 32; i += 256) {
        int r = i >> 5, c = i & 31;
        float4 v = *reinterpret_cast<const float4*>(Qb + r * DD_ + c * 4);
        *reinterpret_cast<float4*>(sQ + r * KS + c * 4) = v;
    }
    for (int i = t; i < TU * 32; i += 256) {
        int r = i >> 5, c = i & 31;
        float4 v = *reinterpret_cast<const float4*>(Kb + r * DD_ + c * 4);
        *reinterpret_cast<float4*>(sK + r * KS + c * 4) = v;
    }
    __syncthreads();

    const int tx = t & 31;     // u-lane
    const int ty = t >> 5;     // n-group (0..7)

    float acc[4][4][4];        // [h][nn][uu]
#pragma unroll
    for (int h = 0; h < 4; h++)
#pragma unroll
        for (int nn = 0; nn < 4; nn++)
#pragma unroll
            for (int uu = 0; uu < 4; uu++) acc[h][nn][uu] = 0.f;

    const float* qb = sQ + (ty * 4) * KS;
    const float* kb = sK + tx * KS;

#pragma unroll
    for (int h = 0; h < 4; h++) {
#pragma unroll 4
        for (int jv = 0; jv < 8; jv++) {
            const int j = h * 32 + jv * 4;
            float4 qf[4], kf[4];
#pragma unroll
            for (int nn = 0; nn < 4; nn++)
                qf[nn] = *reinterpret_cast<const float4*>(qb + nn * KS + j);
#pragma unroll
            for (int uu = 0; uu < 4; uu++)
                kf[uu] = *reinterpret_cast<const float4*>(kb + uu * 32 * KS + j);
#pragma unroll
            for (int nn = 0; nn < 4; nn++)
#pragma unroll
                for (int uu = 0; uu < 4; uu++) {
                    float a = acc[h][nn][uu];
                    a = fmaf(qf[nn].x, kf[uu].x, a);
                    a = fmaf(qf[nn].y, kf[uu].y, a);
                    a = fmaf(qf[nn].z, kf[uu].z, a);
                    a = fmaf(qf[nn].w, kf[uu].w, a);
                    acc[h][nn][uu] = a;
                }
        }
    }

    // epilogue: head mix + relu + residual-sum
    float w[4][4], bb[4];
#pragma unroll
    for (int o = 0; o < 4; o++) {
        bb[o] = __ldg(mlp_b + o);
#pragma unroll
        for (int h = 0; h < 4; h++) w[o][h] = __ldg(mlp_w + o * 4 + h);
    }

#pragma unroll
    for (int nn = 0; nn < 4; nn++) {
        const size_t base = ((size_t)b * NODES_ + (n0 + ty * 4 + nn)) * U_ + u0 + tx;
#pragma unroll
        for (int uu = 0; uu < 4; uu++) {
            float d0 = acc[0][nn][uu], d1 = acc[1][nn][uu];
            float d2 = acc[2][nn][uu], d3 = acc[3][nn][uu];
            float s = (d0 + d1) + (d2 + d3);
#pragma unroll
            for (int o = 0; o < 4; o++) {
                float c = fmaf(w[o][3], d3, fmaf(w[o][2], d2,
                          fmaf(w[o][1], d1, fmaf(w[o][0], d0, bb[o]))));
                s += fmaxf(c, 0.0f);
            }
            g_S[base + (size_t)uu * 32] = s;
        }
    }
}

// ---------------------------------------------------------------------------
// Kernel 3: per-row zero + exact top-32 select + scatter. One warp per row.
// Finds the 32nd-largest via 32-bit bitwise binary search on order-preserving
// uint keys (exact), writes all strictly-greater, then equals by smallest u
// (matches jax.lax.top_k tie-break). Scatter order is irrelevant (into zeros).
// ---------------------------------------------------------------------------
__global__ __launch_bounds__(256) void topk_kernel(float* __restrict__ out)
{
    const int row  = (int)((blockIdx.x * blockDim.x + threadIdx.x) >> 5); // 0..16383
    const int lane = threadIdx.x & 31;

    const float* srow = g_S + (size_t)row * U_;
    float*       orow = out + (size_t)row * NODES_;

    // zero the full 2048-wide output row
    float4 z = make_float4(0.f, 0.f, 0.f, 0.f);
    float4* o4 = reinterpret_cast<float4*>(orow);
#pragma unroll
    for (int i = 0; i < 16; i++) o4[i * 32 + lane] = z;

    // load scores as order-preserving uints; u = i*32 + lane
    unsigned int ords[32];
#pragma unroll
    for (int i = 0; i < 32; i++) {
        unsigned int bbits = __float_as_uint(srow[i * 32 + lane]);
        ords[i] = bbits ^ ((unsigned int)(((int)bbits) >> 31) | 0x80000000u);
    }

    // T = 32nd-largest ord value (largest T with count(ord >= T) >= 32)
    unsigned int T = 0u;
    for (int bit = 31; bit >= 0; --bit) {
        unsigned int cand = T | (1u << bit);
        int cnt = 0;
#pragma unroll
        for (int i = 0; i < 32; i++) cnt += (ords[i] >= cand) ? 1 : 0;
        cnt = __reduce_add_sync(0xffffffffu, cnt);
        if (cnt >= 32) T = cand;
    }

    int cg = 0;
#pragma unroll
    for (int i = 0; i < 32; i++) cg += (ords[i] > T) ? 1 : 0;
    cg = __reduce_add_sync(0xffffffffu, cg);
    int need_eq = 32 - cg;

    __syncwarp();   // orders the zero-stores before the scatter-stores (warp-scope mem barrier)

    // strictly greater: all selected
#pragma unroll
    for (int i = 0; i < 32; i++) {
        if (ords[i] > T) {
            unsigned int o = ords[i];
            unsigned int bbits = o ^ ((((int)o) >= 0) ? 0xFFFFFFFFu : 0x80000000u);
            orow[i * 32 + lane] = __uint_as_float(bbits);
        }
    }
    // equal to T: take smallest u first (u ascending = i major, lane minor)
    unsigned int lt = (1u << lane) - 1u;
#pragma unroll
    for (int i = 0; i < 32; i++) {
        bool eq = (ords[i] == T);
        unsigned int m = __ballot_sync(0xffffffffu, eq);
        int prior = __popc(m & lt);
        if (eq && prior < need_eq) {
            unsigned int o = ords[i];
            unsigned int bbits = o ^ ((((int)o) >= 0) ? 0xFFFFFFFFu : 0x80000000u);
            orow[i * 32 + lane] = __uint_as_float(bbits);
        }
        int taken = __popc(m);
        need_eq -= (taken < need_eq) ? taken : need_eq;
    }
}

// ---------------------------------------------------------------------------
extern "C" void kernel_launch(void* const* d_in, const int* in_sizes, int n_in,
                              void* d_out, int out_size)
{
    // attribute set first (host-side, not an enqueued op; legal under capture)
    cudaFuncSetAttribute(scores_kernel,
                         cudaFuncAttributeMaxDynamicSharedMemorySize, SMEM_BYTES);

    const float* x     = (const float*)d_in[0];
    const float* Wq    = (const float*)d_in[1];
    const float* bq    = (const float*)d_in[2];
    const float* Wk    = (const float*)d_in[3];
    const float* bk    = (const float*)d_in[4];
    const float* mlp_w = (const float*)d_in[5];
    const float* mlp_b = (const float*)d_in[6];
    // d_in[7] = ln_g, d_in[8] = ln_b : unused (dead adj_static branch)
    float* out = (float*)d_out;

    qk_kernel<<<2048, 128>>>(x, Wq, bq, Wk, bk);

    scores_kernel<<<dim3(U_ / TU, NODES_ / TN, B_), 256, SMEM_BYTES>>>(mlp_w, mlp_b);

    topk_kernel<<<2048, 256>>>(out);
}

// round 15
// speedup vs baseline: 1.2173x; 1.2173x over previous
#include <cuda_runtime.h>

#define B_     8
#define NODES_ 2048
#define U_     1024
#define IND_   64
#define DD_    128

typedef unsigned long long u64;

// packed fp32x2 helpers (sm_100+ PTX)
#define FMA_F32X2(d, a, b, c) \
    asm("fma.rn.f32x2 %0, %1, %2, %3;" : "=l"(d) : "l"(a), "l"(b), "l"(c))
#define PACK2(out, lo, hi) \
    asm("mov.b64 %0, {%1, %2};" : "=l"(out) : "f"(lo), "f"(hi))
#define UNPACK2(lo, hi, in) \
    asm("mov.b64 {%0, %1}, %2;" : "=f"(lo), "=f"(hi) : "l"(in))

// Scratch (device globals: allocation-free rule)
__device__ float g_Q[B_ * NODES_ * DD_];              // scaled Q, 8 MB
__device__ float g_K[B_ * U_ * DD_];                  // K (first 1024 nodes), 4 MB
__device__ float g_S[(size_t)B_ * NODES_ * U_];       // scores, 64 MB

// ---------------------------------------------------------------------------
// Kernel 1: Q/K projections as a shared-memory GEMM.
//   q = (x@Wq.T + bq) * 1/sqrt(32)   (blocks 0..255, 64 rows each)
//   k =  x@Wk.T + bk                 (blocks 256..383, rows with n<1024 only)
// ---------------------------------------------------------------------------
#define QK_WS 68
#define QK_SMEM_BYTES ((128 + 64) * QK_WS * 4)

extern __shared__ float qk_sm[];

__global__ __launch_bounds__(256) void qk_kernel(
    const float* __restrict__ x,
    const float* __restrict__ Wq, const float* __restrict__ bq,
    const float* __restrict__ Wk, const float* __restrict__ bk)
{
    float* sW = qk_sm;                 // 128 x QK_WS
    float* sX = qk_sm + 128 * QK_WS;   // 64 x QK_WS

    const int t   = threadIdx.x;
    const int blk = blockIdx.x;
    const bool is_q = (blk < 256);

    int row;                                  // flattened (b*2048+n), start of 64-row tile
    const float* W; const float* bias;
    if (is_q) {
        row = blk * 64;
        W = Wq; bias = bq;
    } else {
        const int idx   = blk - 256;          // 0..127
        const int batch = idx >> 4;
        const int nblk  = idx & 15;           // n in [0,1024): 16 tiles of 64
        row = batch * NODES_ + nblk * 64;
        W = Wk; bias = bk;
    }

    for (int i = t; i < 128 * 16; i += 256) {             // W: 128 rows x 16 float4
        int r = i >> 4, c = i & 15;
        float4 v = *reinterpret_cast<const float4*>(W + r * IND_ + c * 4);
        *reinterpret_cast<float4*>(sW + r * QK_WS + c * 4) = v;
    }
    for (int i = t; i < 64 * 16; i += 256) {              // X: 64 rows x 16 float4
        int r = i >> 4, c = i & 15;
        float4 v = *reinterpret_cast<const float4*>(x + ((size_t)(row + r)) * IND_ + c * 4);
        *reinterpret_cast<float4*>(sX + r * QK_WS + c * 4) = v;
    }
    __syncthreads();

    const int tx = t & 15;     // dd = tx + j*16, j=0..7
    const int ty = t >> 4;     // rows ty*4 .. ty*4+3

    float acc[4][8];
#pragma unroll
    for (int nn = 0; nn < 4; nn++)
#pragma unroll
        for (int j = 0; j < 8; j++) acc[nn][j] = 0.f;

    const float* xb = sX + (ty * 4) * QK_WS;
    const float* wb = sW + tx * QK_WS;

#pragma unroll 4
    for (int k4 = 0; k4 < 16; k4++) {
        float4 xv[4];
#pragma unroll
        for (int nn = 0; nn < 4; nn++)
            xv[nn] = *reinterpret_cast<const float4*>(xb + nn * QK_WS + k4 * 4);
#pragma unroll
        for (int j = 0; j < 8; j++) {
            float4 w4 = *reinterpret_cast<const float4*>(wb + j * 16 * QK_WS + k4 * 4);
#pragma unroll
            for (int nn = 0; nn < 4; nn++) {
                float a = acc[nn][j];
                a = fmaf(xv[nn].x, w4.x, a);
                a = fmaf(xv[nn].y, w4.y, a);
                a = fmaf(xv[nn].z, w4.z, a);
                a = fmaf(xv[nn].w, w4.w, a);
                acc[nn][j] = a;
            }
        }
    }

    const float inv = 0.17677669529663689f;   // 1/sqrt(32)
    float bl[8];
#pragma unroll
    for (int j = 0; j < 8; j++) bl[j] = __ldg(bias + tx + j * 16);

    if (is_q) {
#pragma unroll
        for (int nn = 0; nn < 4; nn++) {
            float* o = g_Q + ((size_t)(row + ty * 4 + nn)) * DD_;
#pragma unroll
            for (int j = 0; j < 8; j++)
                o[tx + j * 16] = (acc[nn][j] + bl[j]) * inv;
        }
    } else {
        const int batch = row >> 11;               // row = batch*2048 + n0, n0 < 1024
        const int n0    = row & 2047;
#pragma unroll
        for (int nn = 0; nn < 4; nn++) {
            float* o = g_K + ((size_t)batch * U_ + n0 + ty * 4 + nn) * DD_;
#pragma unroll
            for (int j = 0; j < 8; j++)
                o[tx + j * 16] = acc[nn][j] + bl[j];
        }
    }
}

// ---------------------------------------------------------------------------
// Kernel 2: scores, fma.rn.f32x2 mainloop (accumulators packed over uu pairs).
//   s = sum_h d_h + sum_o relu( sum_h w[o,h]*d_h + b[o] )
// Tile: 32 n x 128 u per CTA, 256 threads, 4n x 4u micro (u = uu*32 + tx).
// ---------------------------------------------------------------------------
#define TN 32
#define TU 128
#define KS 132   // 33 x 16B granules; 33 mod 8 == 1 -> no LDS.128 conflicts
#define SMEM_BYTES ((TN + TU) * KS * 4)

extern __shared__ float smem2[];

__global__ __launch_bounds__(256, 2) void scores_kernel(
    const float* __restrict__ mlp_w, const float* __restrict__ mlp_b)
{
    float* sQ = smem2;                 // TN x KS
    float* sK = smem2 + TN * KS;       // TU x KS

    const int b  = blockIdx.z;
    const int n0 = blockIdx.y * TN;
    const int u0 = blockIdx.x * TU;
    const int t  = threadIdx.x;

    const float* Qb = g_Q + ((size_t)b * NODES_ + n0) * DD_;
    const float* Kb = g_K + ((size_t)b * U_ + u0) * DD_;

    for (int i = t; i < TN * 32; i += 256) {
        int r = i >> 5, c = i & 31;
        float4 v = *reinterpret_cast<const float4*>(Qb + r * DD_ + c * 4);
        *reinterpret_cast<float4*>(sQ + r * KS + c * 4) = v;
    }
    for (int i = t; i < TU * 32; i += 256) {
        int r = i >> 5, c = i & 31;
        float4 v = *reinterpret_cast<const float4*>(Kb + r * DD_ + c * 4);
        *reinterpret_cast<float4*>(sK + r * KS + c * 4) = v;
    }
    __syncthreads();

    const int tx = t & 31;     // u-lane
    const int ty = t >> 5;     // n-group (0..7)

    // packed accumulators: accp[h][nn][p], p=0 -> (uu0,uu1), p=1 -> (uu2,uu3)
    u64 accp[4][4][2];
#pragma unroll
    for (int h = 0; h < 4; h++)
#pragma unroll
        for (int nn = 0; nn < 4; nn++) {
            accp[h][nn][0] = 0ull;
            accp[h][nn][1] = 0ull;
        }

    const float* qb = sQ + (ty * 4) * KS;
    const float* kb = sK + tx * KS;

#pragma unroll
    for (int h = 0; h < 4; h++) {
#pragma unroll 4
        for (int jv = 0; jv < 8; jv++) {
            const int j = h * 32 + jv * 4;
            float4 qf[4], kf[4];
#pragma unroll
            for (int nn = 0; nn < 4; nn++)
                qf[nn] = *reinterpret_cast<const float4*>(qb + nn * KS + j);
#pragma unroll
            for (int uu = 0; uu < 4; uu++)
                kf[uu] = *reinterpret_cast<const float4*>(kb + uu * 32 * KS + j);

            const float* qe[4] = { (const float*)&qf[0], (const float*)&qf[1],
                                   (const float*)&qf[2], (const float*)&qf[3] };
            const float* ke[4] = { (const float*)&kf[0], (const float*)&kf[1],
                                   (const float*)&kf[2], (const float*)&kf[3] };
#pragma unroll
            for (int e = 0; e < 4; e++) {
                u64 kp0, kp1;
                PACK2(kp0, ke[0][e], ke[1][e]);
                PACK2(kp1, ke[2][e], ke[3][e]);
#pragma unroll
                for (int nn = 0; nn < 4; nn++) {
                    u64 qd;
                    PACK2(qd, qe[nn][e], qe[nn][e]);
                    FMA_F32X2(accp[h][nn][0], qd, kp0, accp[h][nn][0]);
                    FMA_F32X2(accp[h][nn][1], qd, kp1, accp[h][nn][1]);
                }
            }
        }
    }

    float w[4][4], bb[4];
#pragma unroll
    for (int o = 0; o < 4; o++) {
        bb[o] = __ldg(mlp_b + o);
#pragma unroll
        for (int h = 0; h < 4; h++) w[o][h] = __ldg(mlp_w + o * 4 + h);
    }

#pragma unroll
    for (int nn = 0; nn < 4; nn++) {
        float dv[4][4];   // [h][uu]
#pragma unroll
        for (int h = 0; h < 4; h++) {
            UNPACK2(dv[h][0], dv[h][1], accp[h][nn][0]);
            UNPACK2(dv[h][2], dv[h][3], accp[h][nn][1]);
        }
        const size_t base = ((size_t)b * NODES_ + (n0 + ty * 4 + nn)) * U_ + u0 + tx;
#pragma unroll
        for (int uu = 0; uu < 4; uu++) {
            float d0 = dv[0][uu], d1 = dv[1][uu];
            float d2 = dv[2][uu], d3 = dv[3][uu];
            float s = (d0 + d1) + (d2 + d3);
#pragma unroll
            for (int o = 0; o < 4; o++) {
                float c = fmaf(w[o][3], d3, fmaf(w[o][2], d2,
                          fmaf(w[o][1], d1, fmaf(w[o][0], d0, bb[o]))));
                s += fmaxf(c, 0.0f);
            }
            g_S[base + (size_t)uu * 32] = s;
        }
    }
}

// ---------------------------------------------------------------------------
// Kernel 3: per-row zero + exact top-32 select + scatter. One warp per row.
// Bitwise threshold search with early exit: once count(ord >= prefix) == 32
// exactly, T = min{ord >= prefix} (one predicated min + warp reduce).
// ---------------------------------------------------------------------------
__global__ __launch_bounds__(256) void topk_kernel(float* __restrict__ out)
{
    const int row  = (int)((blockIdx.x * blockDim.x + threadIdx.x) >> 5); // 0..16383
    const int lane = threadIdx.x & 31;

    const float* srow = g_S + (size_t)row * U_;
    float*       orow = out + (size_t)row * NODES_;

    float4 z = make_float4(0.f, 0.f, 0.f, 0.f);
    float4* o4 = reinterpret_cast<float4*>(orow);
#pragma unroll
    for (int i = 0; i < 16; i++) o4[i * 32 + lane] = z;

    unsigned int ords[32];
#pragma unroll
    for (int i = 0; i < 32; i++) {
        unsigned int bbits = __float_as_uint(srow[i * 32 + lane]);
        ords[i] = bbits ^ ((unsigned int)(((int)bbits) >> 31) | 0x80000000u);
    }

    // T = 32nd-largest ord (largest T with count(ord >= T) >= 32).
    unsigned int T = 0u;
    for (int bit = 31; bit >= 0; --bit) {
        unsigned int cand = T | (1u << bit);
        int cnt = 0;
#pragma unroll
        for (int i = 0; i < 32; i++) cnt += (ords[i] >= cand) ? 1 : 0;
        cnt = __reduce_add_sync(0xffffffffu, cnt);
        if (cnt >= 32) {
            T = cand;
            if (cnt == 32) {
                // exactly 32 elements >= T: the 32nd-largest is their minimum
                unsigned int mn = 0xFFFFFFFFu;
#pragma unroll
                for (int i = 0; i < 32; i++)
                    if (ords[i] >= T && ords[i] < mn) mn = ords[i];
                T = __reduce_min_sync(0xffffffffu, mn);
                break;
            }
        }
    }

    int cg = 0;
#pragma unroll
    for (int i = 0; i < 32; i++) cg += (ords[i] > T) ? 1 : 0;
    cg = __reduce_add_sync(0xffffffffu, cg);
    int need_eq = 32 - cg;

    __syncwarp();

#pragma unroll
    for (int i = 0; i < 32; i++) {
        if (ords[i] > T) {
            unsigned int o = ords[i];
            unsigned int bbits = o ^ ((((int)o) >= 0) ? 0xFFFFFFFFu : 0x80000000u);
            orow[i * 32 + lane] = __uint_as_float(bbits);
        }
    }
    unsigned int lt = (1u << lane) - 1u;
#pragma unroll
    for (int i = 0; i < 32; i++) {
        bool eq = (ords[i] == T);
        unsigned int m = __ballot_sync(0xffffffffu, eq);
        int prior = __popc(m & lt);
        if (eq && prior < need_eq) {
            unsigned int o = ords[i];
            unsigned int bbits = o ^ ((((int)o) >= 0) ? 0xFFFFFFFFu : 0x80000000u);
            orow[i * 32 + lane] = __uint_as_float(bbits);
        }
        int taken = __popc(m);
        need_eq -= (taken < need_eq) ? taken : need_eq;
    }
}

// ---------------------------------------------------------------------------
extern "C" void kernel_launch(void* const* d_in, const int* in_sizes, int n_in,
                              void* d_out, int out_size)
{
    cudaFuncSetAttribute(qk_kernel,
                         cudaFuncAttributeMaxDynamicSharedMemorySize, QK_SMEM_BYTES);
    cudaFuncSetAttribute(scores_kernel,
                         cudaFuncAttributeMaxDynamicSharedMemorySize, SMEM_BYTES);

    const float* x     = (const float*)d_in[0];
    const float* Wq    = (const float*)d_in[1];
    const float* bq    = (const float*)d_in[2];
    const float* Wk    = (const float*)d_in[3];
    const float* bk    = (const float*)d_in[4];
    const float* mlp_w = (const float*)d_in[5];
    const float* mlp_b = (const float*)d_in[6];
    // d_in[7] = ln_g, d_in[8] = ln_b : unused (dead adj_static branch)
    float* out = (float*)d_out;

    qk_kernel<<<384, 256, QK_SMEM_BYTES>>>(x, Wq, bq, Wk, bk);

    scores_kernel<<<dim3(U_ / TU, NODES_ / TN, B_), 256, SMEM_BYTES>>>(mlp_w, mlp_b);

    topk_kernel<<<2048, 256>>>(out);
}